// round 1
// baseline (speedup 1.0000x reference)
#include <cuda_runtime.h>
#include <cuda_bf16.h>
#include <cstdint>

// Problem constants
#define BB 2
#define SS 2048
#define DD 768
#define HH 12
#define DKK 64
#define NT (BB*SS)            // 4096 token rows
#define OUT_OFF ((size_t)BB*SS*DD)   // attn starts after output in d_out

// Scratch (allocation-free rule: __device__ globals)
__device__ float g_Q[NT*DD];
__device__ float g_K[NT*DD];
__device__ float g_V[NT*DD];
__device__ float g_ctx[NT*DD];

// ---------------------------------------------------------------------------
// GEMM: C[m,n] = sum_k X[m,k] * W[n,k]  (+ optional bias), row-major everything
// Tiles: 128x128x8, 256 threads, 8x8 microtile
// ---------------------------------------------------------------------------
__global__ __launch_bounds__(256)
void gemm_nt_kernel(const float* __restrict__ X, const float* __restrict__ W,
                    float* __restrict__ C, const float* __restrict__ bias,
                    int M, int N, int K)
{
    __shared__ float As[8][128];
    __shared__ float Bs[8][128];

    const int tid = threadIdx.x;
    const int tx = tid & 15;        // 0..15  -> 8 cols each
    const int ty = tid >> 4;        // 0..15  -> 8 rows each
    const int m0 = blockIdx.y * 128;
    const int n0 = blockIdx.x * 128;

    float acc[8][8];
#pragma unroll
    for (int i = 0; i < 8; i++)
#pragma unroll
        for (int j = 0; j < 8; j++) acc[i][j] = 0.f;

    const int lr = tid >> 1;            // 0..127
    const int lk = (tid & 1) * 4;       // 0 or 4

    for (int k0 = 0; k0 < K; k0 += 8) {
        float4 va = *(const float4*)&X[(size_t)(m0 + lr) * K + k0 + lk];
        float4 vb = *(const float4*)&W[(size_t)(n0 + lr) * K + k0 + lk];
        As[lk+0][lr] = va.x; As[lk+1][lr] = va.y; As[lk+2][lr] = va.z; As[lk+3][lr] = va.w;
        Bs[lk+0][lr] = vb.x; Bs[lk+1][lr] = vb.y; Bs[lk+2][lr] = vb.z; Bs[lk+3][lr] = vb.w;
        __syncthreads();

#pragma unroll
        for (int kk = 0; kk < 8; kk++) {
            float a[8], b[8];
            *(float4*)&a[0] = *(float4*)&As[kk][ty*8];
            *(float4*)&a[4] = *(float4*)&As[kk][ty*8+4];
            *(float4*)&b[0] = *(float4*)&Bs[kk][tx*8];
            *(float4*)&b[4] = *(float4*)&Bs[kk][tx*8+4];
#pragma unroll
            for (int i = 0; i < 8; i++)
#pragma unroll
                for (int j = 0; j < 8; j++)
                    acc[i][j] += a[i] * b[j];
        }
        __syncthreads();
    }

#pragma unroll
    for (int i = 0; i < 8; i++) {
        int m = m0 + ty*8 + i;
#pragma unroll
        for (int j = 0; j < 8; j += 4) {
            int n = n0 + tx*8 + j;
            float4 v;
            v.x = acc[i][j+0]; v.y = acc[i][j+1]; v.z = acc[i][j+2]; v.w = acc[i][j+3];
            if (bias) {
                v.x += bias[n+0]; v.y += bias[n+1]; v.z += bias[n+2]; v.w += bias[n+3];
            }
            *(float4*)&C[(size_t)m * N + n] = v;
        }
    }
}

// ---------------------------------------------------------------------------
// Fused attention: one block = (b, h, 16 query rows)
// Full 16x2048 score row kept in smem; K/V streamed in 64x64 chunks.
// Writes normalized attn to d_out and context to g_ctx.
// 512 threads, dynamic smem = 151808 B
// ---------------------------------------------------------------------------
#define QT 16
#define KC 64
#define KVPAD 65   // 64+1, conflict-free column reads

__global__ __launch_bounds__(512)
void attn_kernel(const float* __restrict__ Q, const float* __restrict__ K,
                 const float* __restrict__ V,
                 const int* __restrict__ mask, const float* __restrict__ pb,
                 float* __restrict__ attn_out, float* __restrict__ ctx)
{
    extern __shared__ float sm[];
    float* sQ  = sm;                   // QT*64      = 1024
    float* sKV = sQ + QT*64;           // 64*65      = 4160
    float* sS  = sKV + 64*KVPAD;       // QT*2048    = 32768

    const int tid = threadIdx.x;
    const int blk = blockIdx.x;
    const int b  = blk % BB;
    const int r1 = blk / BB;
    const int h  = r1 % HH;
    const int qt = r1 / HH;
    const int q0 = qt * QT;

    const size_t rowQ = (size_t)(b*SS + q0) * DD + h*DKK;

    // ---- load Q tile (16 x 64) ----
    for (int e = tid; e < QT*16; e += blockDim.x) {
        int r = e >> 4, c4 = (e & 15) * 4;
        float4 v = *(const float4*)&Q[rowQ + (size_t)r*DD + c4];
        *(float4*)&sQ[r*64 + c4] = v;
    }

    const int kc = tid & 63;     // key col within chunk / head-dim col
    const int ty = tid >> 6;     // 0..7 -> query rows ty and ty+8

    // ---- scores: S = QK^T/8 + pos_bias, masked ----
    for (int kt = 0; kt < SS/KC; kt++) {
        const int k0 = kt * KC;
        __syncthreads();   // protect sKV reuse
        for (int e = tid; e < KC*16; e += blockDim.x) {
            int r = e >> 4, c4 = (e & 15) * 4;
            float4 v = *(const float4*)&K[(size_t)(b*SS + k0 + r)*DD + h*DKK + c4];
            float* dst = &sKV[r*KVPAD + c4];
            dst[0]=v.x; dst[1]=v.y; dst[2]=v.z; dst[3]=v.w;
        }
        __syncthreads();

        float a0 = 0.f, a1 = 0.f;
#pragma unroll
        for (int d = 0; d < DKK; d++) {
            float kv = sKV[kc*KVPAD + d];
            a0 += sQ[ty*64 + d]       * kv;
            a1 += sQ[(ty+8)*64 + d]   * kv;
        }
        const int gq0 = q0 + ty, gq1 = q0 + ty + 8, gk = k0 + kc;
        float s0 = a0 * 0.125f + pb[((size_t)h*SS + gq0)*SS + gk];
        float s1 = a1 * 0.125f + pb[((size_t)h*SS + gq1)*SS + gk];
        if (mask[((size_t)b*SS + gq0)*SS + gk] == 0) s0 = -1e9f;
        if (mask[((size_t)b*SS + gq1)*SS + gk] == 0) s1 = -1e9f;
        sS[ty*SS + gk]     = s0;
        sS[(ty+8)*SS + gk] = s1;
    }
    __syncthreads();

    // ---- softmax: warp w handles row w (16 warps) ----
    {
        const int warp = tid >> 5, lane = tid & 31;
        float* row = &sS[warp * SS];
        float m = -1e30f;
        for (int c = lane*4; c < SS; c += 128) {
            float4 v = *(const float4*)&row[c];
            m = fmaxf(m, fmaxf(fmaxf(v.x, v.y), fmaxf(v.z, v.w)));
        }
#pragma unroll
        for (int o = 16; o; o >>= 1) m = fmaxf(m, __shfl_xor_sync(0xffffffffu, m, o));
        float sum = 0.f;
        for (int c = lane*4; c < SS; c += 128) {
            float4 v = *(const float4*)&row[c];
            v.x = __expf(v.x - m); v.y = __expf(v.y - m);
            v.z = __expf(v.z - m); v.w = __expf(v.w - m);
            sum += v.x + v.y + v.z + v.w;
            *(float4*)&row[c] = v;
        }
#pragma unroll
        for (int o = 16; o; o >>= 1) sum += __shfl_xor_sync(0xffffffffu, sum, o);
        const float rinv = 1.f / sum;
        float* aout = &attn_out[(((size_t)b*HH + h)*SS + q0 + warp)*SS];
        for (int c = lane*4; c < SS; c += 128) {
            float4 v = *(const float4*)&row[c];
            v.x *= rinv; v.y *= rinv; v.z *= rinv; v.w *= rinv;
            *(float4*)&row[c] = v;
            *(float4*)&aout[c] = v;
        }
    }
    __syncthreads();

    // ---- context: ctx = P @ V  (16 x 64 per block) ----
    float c0 = 0.f, c1 = 0.f;
    for (int kt = 0; kt < SS/KC; kt++) {
        const int k0 = kt * KC;
        __syncthreads();   // protect sKV reuse
        for (int e = tid; e < KC*16; e += blockDim.x) {
            int r = e >> 4, c4 = (e & 15) * 4;
            float4 v = *(const float4*)&V[(size_t)(b*SS + k0 + r)*DD + h*DKK + c4];
            float* dst = &sKV[r*KVPAD + c4];
            dst[0]=v.x; dst[1]=v.y; dst[2]=v.z; dst[3]=v.w;
        }
        __syncthreads();
#pragma unroll
        for (int kk = 0; kk < KC; kk++) {
            float vv = sKV[kk*KVPAD + kc];
            c0 += sS[ty*SS + k0 + kk]     * vv;
            c1 += sS[(ty+8)*SS + k0 + kk] * vv;
        }
    }
    ctx[(size_t)(b*SS + q0 + ty)*DD     + h*DKK + kc] = c0;
    ctx[(size_t)(b*SS + q0 + ty + 8)*DD + h*DKK + kc] = c1;
}

// ---------------------------------------------------------------------------
// Launch
// ---------------------------------------------------------------------------
extern "C" void kernel_launch(void* const* d_in, const int* in_sizes, int n_in,
                              void* d_out, int out_size)
{
    const float* query = (const float*)d_in[0];
    const float* key   = (const float*)d_in[1];
    const float* value = (const float*)d_in[2];
    const int*   mask  = (const int*)  d_in[3];
    const float* pb    = (const float*)d_in[4];
    const float* Wq    = (const float*)d_in[5];
    const float* Wk    = (const float*)d_in[6];
    const float* Wv    = (const float*)d_in[7];
    const float* Wo    = (const float*)d_in[8];
    const float* bo    = (const float*)d_in[9];
    float* out = (float*)d_out;

    float *pQ, *pK, *pV, *pC;
    cudaGetSymbolAddress((void**)&pQ, g_Q);
    cudaGetSymbolAddress((void**)&pK, g_K);
    cudaGetSymbolAddress((void**)&pV, g_V);
    cudaGetSymbolAddress((void**)&pC, g_ctx);

    const int ATTN_SMEM = (QT*64 + 64*KVPAD + QT*SS) * sizeof(float); // 151808
    cudaFuncSetAttribute(attn_kernel, cudaFuncAttributeMaxDynamicSharedMemorySize, ATTN_SMEM);

    dim3 gg(DD/128, NT/128);   // (6, 32)
    gemm_nt_kernel<<<gg, 256>>>(query, Wq, pQ, nullptr, NT, DD, DD);
    gemm_nt_kernel<<<gg, 256>>>(key,   Wk, pK, nullptr, NT, DD, DD);
    gemm_nt_kernel<<<gg, 256>>>(value, Wv, pV, nullptr, NT, DD, DD);

    attn_kernel<<<BB*HH*(SS/QT), 512, ATTN_SMEM>>>(pQ, pK, pV, mask, pb,
                                                   out + OUT_OFF, pC);

    gemm_nt_kernel<<<gg, 256>>>(pC, Wo, out, bo, NT, DD, DD);
}

// round 3
// speedup vs baseline: 1.8283x; 1.8283x over previous
#include <cuda_runtime.h>
#include <cuda_bf16.h>
#include <cstdint>

// Problem constants
#define BB 2
#define SS 2048
#define DD 768
#define HH 12
#define DKK 64
#define NT (BB*SS)
#define OUT_OFF ((size_t)BB*SS*DD)

#define SPAD 2060   // sS row stride (pad 12 -> conflict-free A-frag loads)
#define KPAD 68     // K/V/Q smem row stride

// Scratch
__device__ float g_Q[NT*DD];
__device__ float g_K[NT*DD];
__device__ float g_V[NT*DD];
__device__ float g_ctx[NT*DD];

// ---------------------------------------------------------------------------
// helpers
// ---------------------------------------------------------------------------
__device__ __forceinline__ uint32_t tf32r(float x) {
    uint32_t u; asm("cvt.rna.tf32.f32 %0, %1;" : "=r"(u) : "f"(x)); return u;
}
__device__ __forceinline__ float tf32f(float x) { return __uint_as_float(tf32r(x)); }

__device__ __forceinline__ void mma8(float* c,
    uint32_t a0, uint32_t a1, uint32_t a2, uint32_t a3, uint32_t b0, uint32_t b1)
{
    asm volatile(
        "mma.sync.aligned.m16n8k8.row.col.f32.tf32.tf32.f32 "
        "{%0,%1,%2,%3},{%4,%5,%6,%7},{%8,%9},{%0,%1,%2,%3};"
        : "+f"(c[0]), "+f"(c[1]), "+f"(c[2]), "+f"(c[3])
        : "r"(a0), "r"(a1), "r"(a2), "r"(a3), "r"(b0), "r"(b1));
}

// ---------------------------------------------------------------------------
// Tensor-core GEMM: C[m,n] = sum_k X[m,k]*W[n,k] (+bias)
// 128x128 tile, 256 threads (8 warps, 2x4), warp tile 64x32.
// PREC=3 -> 3xTF32 (hi/lo split), PREC=1 -> plain tf32.
// ---------------------------------------------------------------------------
template<int PREC>
__global__ __launch_bounds__(256)
void gemm_tc(const float* __restrict__ X, const float* __restrict__ W,
             float* __restrict__ C, const float* __restrict__ bias,
             int M, int N, int K)
{
    __shared__ float As[16][132];
    __shared__ float Bs[16][132];

    const int tid  = threadIdx.x;
    const int lane = tid & 31, warp = tid >> 5;
    const int g = lane >> 2, l4 = lane & 3;
    const int wm = warp >> 2, wn = warp & 3;
    const int m0 = blockIdx.y * 128, n0 = blockIdx.x * 128;

    float acc[4][4][4];
#pragma unroll
    for (int i = 0; i < 4; i++)
#pragma unroll
        for (int j = 0; j < 4; j++)
#pragma unroll
            for (int r = 0; r < 4; r++) acc[i][j][r] = 0.f;

    for (int k0 = 0; k0 < K; k0 += 16) {
#pragma unroll
        for (int i = 0; i < 2; i++) {
            int ii = tid + i * 256;
            int row = ii >> 2, kg = (ii & 3) * 4;
            float4 av = *(const float4*)&X[(size_t)(m0 + row) * K + k0 + kg];
            float4 bv = *(const float4*)&W[(size_t)(n0 + row) * K + k0 + kg];
            if (PREC == 1) {
                As[kg+0][row] = tf32f(av.x); As[kg+1][row] = tf32f(av.y);
                As[kg+2][row] = tf32f(av.z); As[kg+3][row] = tf32f(av.w);
                Bs[kg+0][row] = tf32f(bv.x); Bs[kg+1][row] = tf32f(bv.y);
                Bs[kg+2][row] = tf32f(bv.z); Bs[kg+3][row] = tf32f(bv.w);
            } else {
                As[kg+0][row] = av.x; As[kg+1][row] = av.y;
                As[kg+2][row] = av.z; As[kg+3][row] = av.w;
                Bs[kg+0][row] = bv.x; Bs[kg+1][row] = bv.y;
                Bs[kg+2][row] = bv.z; Bs[kg+3][row] = bv.w;
            }
        }
        __syncthreads();

#pragma unroll
        for (int ks = 0; ks < 2; ks++) {
            uint32_t ah[4][4], al[4][4], bh[4][2], bl[4][2];
#pragma unroll
            for (int mt = 0; mt < 4; mt++) {
                int rb = wm * 64 + mt * 16;
                float f0 = As[ks*8 + l4][rb + g];
                float f1 = As[ks*8 + l4][rb + g + 8];
                float f2 = As[ks*8 + l4 + 4][rb + g];
                float f3 = As[ks*8 + l4 + 4][rb + g + 8];
                if (PREC == 3) {
                    ah[mt][0] = tf32r(f0); al[mt][0] = tf32r(f0 - __uint_as_float(ah[mt][0]));
                    ah[mt][1] = tf32r(f1); al[mt][1] = tf32r(f1 - __uint_as_float(ah[mt][1]));
                    ah[mt][2] = tf32r(f2); al[mt][2] = tf32r(f2 - __uint_as_float(ah[mt][2]));
                    ah[mt][3] = tf32r(f3); al[mt][3] = tf32r(f3 - __uint_as_float(ah[mt][3]));
                } else {
                    ah[mt][0] = __float_as_uint(f0); ah[mt][1] = __float_as_uint(f1);
                    ah[mt][2] = __float_as_uint(f2); ah[mt][3] = __float_as_uint(f3);
                }
            }
#pragma unroll
            for (int nt = 0; nt < 4; nt++) {
                int cb = wn * 32 + nt * 8;
                float f0 = Bs[ks*8 + l4][cb + g];
                float f1 = Bs[ks*8 + l4 + 4][cb + g];
                if (PREC == 3) {
                    bh[nt][0] = tf32r(f0); bl[nt][0] = tf32r(f0 - __uint_as_float(bh[nt][0]));
                    bh[nt][1] = tf32r(f1); bl[nt][1] = tf32r(f1 - __uint_as_float(bh[nt][1]));
                } else {
                    bh[nt][0] = __float_as_uint(f0); bh[nt][1] = __float_as_uint(f1);
                }
            }
#pragma unroll
            for (int mt = 0; mt < 4; mt++)
#pragma unroll
                for (int nt = 0; nt < 4; nt++) {
                    if (PREC == 3) {
                        mma8(acc[mt][nt], al[mt][0], al[mt][1], al[mt][2], al[mt][3],
                             bh[nt][0], bh[nt][1]);
                        mma8(acc[mt][nt], ah[mt][0], ah[mt][1], ah[mt][2], ah[mt][3],
                             bl[nt][0], bl[nt][1]);
                    }
                    mma8(acc[mt][nt], ah[mt][0], ah[mt][1], ah[mt][2], ah[mt][3],
                         bh[nt][0], bh[nt][1]);
                }
        }
        __syncthreads();
    }

    // epilogue
#pragma unroll
    for (int mt = 0; mt < 4; mt++) {
        int r0 = m0 + wm * 64 + mt * 16 + g;
#pragma unroll
        for (int nt = 0; nt < 4; nt++) {
            int cc = n0 + wn * 32 + nt * 8 + 2 * l4;
            float bx = 0.f, by = 0.f;
            if (bias) { bx = bias[cc]; by = bias[cc + 1]; }
            float2 v0 = make_float2(acc[mt][nt][0] + bx, acc[mt][nt][1] + by);
            float2 v1 = make_float2(acc[mt][nt][2] + bx, acc[mt][nt][3] + by);
            *(float2*)&C[(size_t)r0 * N + cc] = v0;
            *(float2*)&C[(size_t)(r0 + 8) * N + cc] = v1;
        }
    }
}

// ---------------------------------------------------------------------------
// Fused attention, tensor-core version.
// Block = (qt, b, h): 16 query rows, 256 threads (8 warps).
// Phase 1: S = QK^T/8 + bias, masked (3xTF32). Phase 2: softmax (+attn out).
// Phase 3: ctx = P @ V (tf32).
// ---------------------------------------------------------------------------
__global__ __launch_bounds__(256)
void attn_tc_kernel(const float* __restrict__ Q, const float* __restrict__ K,
                    const float* __restrict__ V,
                    const int* __restrict__ mask, const float* __restrict__ pb,
                    float* __restrict__ attn_out, float* __restrict__ ctx)
{
    extern __shared__ float sm[];
    float* sQh = sm;                    // 16*KPAD
    float* sQl = sQh + 16 * KPAD;       // 16*KPAD
    float* sKh = sQl + 16 * KPAD;       // 128*KPAD  (V reuses this in phase 3)
    float* sKl = sKh + 128 * KPAD;      // 128*KPAD
    float* sS  = sKl + 128 * KPAD;      // 16*SPAD

    const int tid  = threadIdx.x;
    const int lane = tid & 31, w = tid >> 5;
    const int g = lane >> 2, l4 = lane & 3;
    const int qt = blockIdx.x, b = blockIdx.y, h = blockIdx.z;
    const int q0 = qt * 16;

    // ---- load Q tile (16x64), hi/lo split ----
    {
        int row = tid >> 4, dg = (tid & 15) * 4;
        float4 v = *(const float4*)&Q[(size_t)(b*SS + q0 + row) * DD + h*DKK + dg];
        float f[4] = {v.x, v.y, v.z, v.w};
#pragma unroll
        for (int j = 0; j < 4; j++) {
            uint32_t hi = tf32r(f[j]);
            sQh[row * KPAD + dg + j] = __uint_as_float(hi);
            sQl[row * KPAD + dg + j] = __uint_as_float(tf32r(f[j] - __uint_as_float(hi)));
        }
    }

    // ---- phase 1: scores ----
    for (int kt = 0; kt < SS / 128; kt++) {
        __syncthreads();
#pragma unroll
        for (int i = 0; i < 8; i++) {
            int idx = tid + i * 256;
            int row = idx >> 4, dg = (idx & 15) * 4;
            float4 v = *(const float4*)&K[(size_t)(b*SS + kt*128 + row) * DD + h*DKK + dg];
            float f[4] = {v.x, v.y, v.z, v.w};
#pragma unroll
            for (int j = 0; j < 4; j++) {
                uint32_t hi = tf32r(f[j]);
                sKh[row * KPAD + dg + j] = __uint_as_float(hi);
                sKl[row * KPAD + dg + j] = __uint_as_float(tf32r(f[j] - __uint_as_float(hi)));
            }
        }
        __syncthreads();

        float acc[2][4] = {{0,0,0,0},{0,0,0,0}};
#pragma unroll
        for (int ks = 0; ks < 8; ks++) {
            int kk = ks * 8 + l4;
            uint32_t ah0 = __float_as_uint(sQh[g * KPAD + kk]);
            uint32_t ah1 = __float_as_uint(sQh[(g+8) * KPAD + kk]);
            uint32_t ah2 = __float_as_uint(sQh[g * KPAD + kk + 4]);
            uint32_t ah3 = __float_as_uint(sQh[(g+8) * KPAD + kk + 4]);
            uint32_t al0 = __float_as_uint(sQl[g * KPAD + kk]);
            uint32_t al1 = __float_as_uint(sQl[(g+8) * KPAD + kk]);
            uint32_t al2 = __float_as_uint(sQl[g * KPAD + kk + 4]);
            uint32_t al3 = __float_as_uint(sQl[(g+8) * KPAD + kk + 4]);
#pragma unroll
            for (int nt = 0; nt < 2; nt++) {
                int key = w * 16 + nt * 8 + g;
                uint32_t bh0 = __float_as_uint(sKh[key * KPAD + kk]);
                uint32_t bh1 = __float_as_uint(sKh[key * KPAD + kk + 4]);
                uint32_t bl0 = __float_as_uint(sKl[key * KPAD + kk]);
                uint32_t bl1 = __float_as_uint(sKl[key * KPAD + kk + 4]);
                mma8(acc[nt], al0, al1, al2, al3, bh0, bh1);
                mma8(acc[nt], ah0, ah1, ah2, ah3, bl0, bl1);
                mma8(acc[nt], ah0, ah1, ah2, ah3, bh0, bh1);
            }
        }

        // epilogue: +pos_bias, mask, store to sS
#pragma unroll
        for (int nt = 0; nt < 2; nt++) {
            int kcol = kt * 128 + w * 16 + nt * 8 + 2 * l4;
            int r0 = q0 + g, r1 = q0 + g + 8;
            float2 pb0 = *(const float2*)&pb[((size_t)h*SS + r0) * SS + kcol];
            float2 pb1 = *(const float2*)&pb[((size_t)h*SS + r1) * SS + kcol];
            int2 mk0 = *(const int2*)&mask[((size_t)b*SS + r0) * SS + kcol];
            int2 mk1 = *(const int2*)&mask[((size_t)b*SS + r1) * SS + kcol];
            float2 s0, s1;
            s0.x = acc[nt][0] * 0.125f + pb0.x; if (mk0.x == 0) s0.x = -1e9f;
            s0.y = acc[nt][1] * 0.125f + pb0.y; if (mk0.y == 0) s0.y = -1e9f;
            s1.x = acc[nt][2] * 0.125f + pb1.x; if (mk1.x == 0) s1.x = -1e9f;
            s1.y = acc[nt][3] * 0.125f + pb1.y; if (mk1.y == 0) s1.y = -1e9f;
            *(float2*)&sS[g * SPAD + kcol] = s0;
            *(float2*)&sS[(g + 8) * SPAD + kcol] = s1;
        }
    }
    __syncthreads();

    // ---- phase 2: softmax (warp w -> rows 2w, 2w+1) ----
#pragma unroll
    for (int rr = 0; rr < 2; rr++) {
        int row = w * 2 + rr;
        float* rp = &sS[row * SPAD];
        float m = -1e30f;
        for (int c = lane * 4; c < SS; c += 128) {
            float4 v = *(const float4*)&rp[c];
            m = fmaxf(m, fmaxf(fmaxf(v.x, v.y), fmaxf(v.z, v.w)));
        }
#pragma unroll
        for (int o = 16; o; o >>= 1) m = fmaxf(m, __shfl_xor_sync(0xffffffffu, m, o));
        float sum = 0.f;
        for (int c = lane * 4; c < SS; c += 128) {
            float4 v = *(const float4*)&rp[c];
            v.x = __expf(v.x - m); v.y = __expf(v.y - m);
            v.z = __expf(v.z - m); v.w = __expf(v.w - m);
            sum += v.x + v.y + v.z + v.w;
            *(float4*)&rp[c] = v;
        }
#pragma unroll
        for (int o = 16; o; o >>= 1) sum += __shfl_xor_sync(0xffffffffu, sum, o);
        float rinv = 1.f / sum;
        float* aout = &attn_out[(((size_t)b*HH + h) * SS + q0 + row) * SS];
        for (int c = lane * 4; c < SS; c += 128) {
            float4 v = *(const float4*)&rp[c];
            v.x *= rinv; v.y *= rinv; v.z *= rinv; v.w *= rinv;
            *(float4*)&rp[c] = v;
            *(float4*)&aout[c] = v;
        }
    }

    // ---- phase 3: ctx = P @ V  (warp w -> dk cols w*8..w*8+7) ----
    float acc3[4] = {0, 0, 0, 0};
    for (int kt = 0; kt < SS / 128; kt++) {
        __syncthreads();
#pragma unroll
        for (int i = 0; i < 8; i++) {
            int idx = tid + i * 256;
            int row = idx >> 4, dg = (idx & 15) * 4;
            float4 v = *(const float4*)&V[(size_t)(b*SS + kt*128 + row) * DD + h*DKK + dg];
            sKh[row * KPAD + dg + 0] = tf32f(v.x);
            sKh[row * KPAD + dg + 1] = tf32f(v.y);
            sKh[row * KPAD + dg + 2] = tf32f(v.z);
            sKh[row * KPAD + dg + 3] = tf32f(v.w);
        }
        __syncthreads();

#pragma unroll
        for (int ks = 0; ks < 16; ks++) {
            int k0 = kt * 128 + ks * 8;
            uint32_t a0 = tf32r(sS[g * SPAD + k0 + l4]);
            uint32_t a1 = tf32r(sS[(g+8) * SPAD + k0 + l4]);
            uint32_t a2 = tf32r(sS[g * SPAD + k0 + l4 + 4]);
            uint32_t a3 = tf32r(sS[(g+8) * SPAD + k0 + l4 + 4]);
            uint32_t b0 = __float_as_uint(sKh[(ks*8 + l4) * KPAD + w*8 + g]);
            uint32_t b1 = __float_as_uint(sKh[(ks*8 + l4 + 4) * KPAD + w*8 + g]);
            mma8(acc3, a0, a1, a2, a3, b0, b1);
        }
    }
    {
        int cc = h * DKK + w * 8 + 2 * l4;
        *(float2*)&ctx[(size_t)(b*SS + q0 + g) * DD + cc] =
            make_float2(acc3[0], acc3[1]);
        *(float2*)&ctx[(size_t)(b*SS + q0 + g + 8) * DD + cc] =
            make_float2(acc3[2], acc3[3]);
    }
}

// ---------------------------------------------------------------------------
// Launch
// ---------------------------------------------------------------------------
extern "C" void kernel_launch(void* const* d_in, const int* in_sizes, int n_in,
                              void* d_out, int out_size)
{
    const float* query = (const float*)d_in[0];
    const float* key   = (const float*)d_in[1];
    const float* value = (const float*)d_in[2];
    const int*   mask  = (const int*)  d_in[3];
    const float* pb    = (const float*)d_in[4];
    const float* Wq    = (const float*)d_in[5];
    const float* Wk    = (const float*)d_in[6];
    const float* Wv    = (const float*)d_in[7];
    const float* Wo    = (const float*)d_in[8];
    const float* bo    = (const float*)d_in[9];
    float* out = (float*)d_out;

    float *pQ, *pK, *pV, *pC;
    cudaGetSymbolAddress((void**)&pQ, g_Q);
    cudaGetSymbolAddress((void**)&pK, g_K);
    cudaGetSymbolAddress((void**)&pV, g_V);
    cudaGetSymbolAddress((void**)&pC, g_ctx);

    const int ATTN_SMEM = (2*16*KPAD + 2*128*KPAD + 16*SPAD) * sizeof(float); // 210176
    cudaFuncSetAttribute(attn_tc_kernel,
                         cudaFuncAttributeMaxDynamicSharedMemorySize, ATTN_SMEM);

    dim3 gg(DD / 128, NT / 128);   // (6, 32)
    gemm_tc<3><<<gg, 256>>>(query, Wq, pQ, nullptr, NT, DD, DD);
    gemm_tc<3><<<gg, 256>>>(key,   Wk, pK, nullptr, NT, DD, DD);
    gemm_tc<1><<<gg, 256>>>(value, Wv, pV, nullptr, NT, DD, DD);

    dim3 ga(SS / 16, BB, HH);      // (128, 2, 12) — h slowest for L2 reuse
    attn_tc_kernel<<<ga, 256, ATTN_SMEM>>>(pQ, pK, pV, mask, pb,
                                           out + OUT_OFF, pC);

    gemm_tc<1><<<gg, 256>>>(pC, Wo, out, bo, NT, DD, DD);
}

// round 4
// speedup vs baseline: 2.2226x; 1.2157x over previous
#include <cuda_runtime.h>
#include <cuda_bf16.h>
#include <cstdint>

// Problem constants
#define BB 2
#define SS 2048
#define DD 768
#define HH 12
#define DKK 64
#define NT (BB*SS)
#define OUT_OFF ((size_t)BB*SS*DD)

// Scratch
__device__ float g_Q[NT*DD];
__device__ float g_K[NT*DD];
__device__ float g_V[NT*DD];
__device__ float g_ctx[NT*DD];

// ---------------------------------------------------------------------------
// helpers
// ---------------------------------------------------------------------------
__device__ __forceinline__ uint32_t tf32r(float x) {
    uint32_t u; asm("cvt.rna.tf32.f32 %0, %1;" : "=r"(u) : "f"(x)); return u;
}
__device__ __forceinline__ float tf32f(float x) { return __uint_as_float(tf32r(x)); }

__device__ __forceinline__ void mma8(float* c,
    uint32_t a0, uint32_t a1, uint32_t a2, uint32_t a3, uint32_t b0, uint32_t b1)
{
    asm volatile(
        "mma.sync.aligned.m16n8k8.row.col.f32.tf32.tf32.f32 "
        "{%0,%1,%2,%3},{%4,%5,%6,%7},{%8,%9},{%0,%1,%2,%3};"
        : "+f"(c[0]), "+f"(c[1]), "+f"(c[2]), "+f"(c[3])
        : "r"(a0), "r"(a1), "r"(a2), "r"(a3), "r"(b0), "r"(b1));
}

// ---------------------------------------------------------------------------
// Tensor-core GEMM (projections / output): C[m,n] = sum_k X[m,k]*W[n,k] (+bias)
// 128x128 tile, 256 threads, warp tile 64x32. hi/lo split done at staging.
// ---------------------------------------------------------------------------
template<int PREC>
__global__ __launch_bounds__(256)
void gemm_tc(const float* __restrict__ X, const float* __restrict__ W,
             float* __restrict__ C, const float* __restrict__ bias,
             int M, int N, int K)
{
    constexpr int NP = (PREC == 3) ? 2 : 1;
    __shared__ float As[NP][16][132];
    __shared__ float Bs[NP][16][132];

    const int tid  = threadIdx.x;
    const int lane = tid & 31, warp = tid >> 5;
    const int g = lane >> 2, l4 = lane & 3;
    const int wm = warp >> 2, wn = warp & 3;
    const int m0 = blockIdx.y * 128, n0 = blockIdx.x * 128;

    float acc[4][4][4];
#pragma unroll
    for (int i = 0; i < 4; i++)
#pragma unroll
        for (int j = 0; j < 4; j++)
#pragma unroll
            for (int r = 0; r < 4; r++) acc[i][j][r] = 0.f;

    for (int k0 = 0; k0 < K; k0 += 16) {
#pragma unroll
        for (int i = 0; i < 2; i++) {
            int ii = tid + i * 256;
            int row = ii >> 2, kg = (ii & 3) * 4;
            float4 av = *(const float4*)&X[(size_t)(m0 + row) * K + k0 + kg];
            float4 bv = *(const float4*)&W[(size_t)(n0 + row) * K + k0 + kg];
            float fa[4] = {av.x, av.y, av.z, av.w};
            float fb[4] = {bv.x, bv.y, bv.z, bv.w};
#pragma unroll
            for (int j = 0; j < 4; j++) {
                if (PREC == 1) {
                    As[0][kg+j][row] = tf32f(fa[j]);
                    Bs[0][kg+j][row] = tf32f(fb[j]);
                } else {
                    uint32_t ha = tf32r(fa[j]), hb = tf32r(fb[j]);
                    As[0][kg+j][row] = __uint_as_float(ha);
                    Bs[0][kg+j][row] = __uint_as_float(hb);
                    As[NP-1][kg+j][row] = __uint_as_float(tf32r(fa[j] - __uint_as_float(ha)));
                    Bs[NP-1][kg+j][row] = __uint_as_float(tf32r(fb[j] - __uint_as_float(hb)));
                }
            }
        }
        __syncthreads();

#pragma unroll
        for (int ks = 0; ks < 2; ks++) {
            uint32_t ah[4][4], al[4][4], bh[4][2], bl[4][2];
#pragma unroll
            for (int mt = 0; mt < 4; mt++) {
                int rb = wm * 64 + mt * 16;
                ah[mt][0] = __float_as_uint(As[0][ks*8 + l4][rb + g]);
                ah[mt][1] = __float_as_uint(As[0][ks*8 + l4][rb + g + 8]);
                ah[mt][2] = __float_as_uint(As[0][ks*8 + l4 + 4][rb + g]);
                ah[mt][3] = __float_as_uint(As[0][ks*8 + l4 + 4][rb + g + 8]);
                if (PREC == 3) {
                    al[mt][0] = __float_as_uint(As[NP-1][ks*8 + l4][rb + g]);
                    al[mt][1] = __float_as_uint(As[NP-1][ks*8 + l4][rb + g + 8]);
                    al[mt][2] = __float_as_uint(As[NP-1][ks*8 + l4 + 4][rb + g]);
                    al[mt][3] = __float_as_uint(As[NP-1][ks*8 + l4 + 4][rb + g + 8]);
                }
            }
#pragma unroll
            for (int nt = 0; nt < 4; nt++) {
                int cb = wn * 32 + nt * 8;
                bh[nt][0] = __float_as_uint(Bs[0][ks*8 + l4][cb + g]);
                bh[nt][1] = __float_as_uint(Bs[0][ks*8 + l4 + 4][cb + g]);
                if (PREC == 3) {
                    bl[nt][0] = __float_as_uint(Bs[NP-1][ks*8 + l4][cb + g]);
                    bl[nt][1] = __float_as_uint(Bs[NP-1][ks*8 + l4 + 4][cb + g]);
                }
            }
#pragma unroll
            for (int mt = 0; mt < 4; mt++)
#pragma unroll
                for (int nt = 0; nt < 4; nt++) {
                    if (PREC == 3) {
                        mma8(acc[mt][nt], al[mt][0], al[mt][1], al[mt][2], al[mt][3],
                             bh[nt][0], bh[nt][1]);
                        mma8(acc[mt][nt], ah[mt][0], ah[mt][1], ah[mt][2], ah[mt][3],
                             bl[nt][0], bl[nt][1]);
                    }
                    mma8(acc[mt][nt], ah[mt][0], ah[mt][1], ah[mt][2], ah[mt][3],
                         bh[nt][0], bh[nt][1]);
                }
        }
        __syncthreads();
    }

#pragma unroll
    for (int mt = 0; mt < 4; mt++) {
        int r0 = m0 + wm * 64 + mt * 16 + g;
#pragma unroll
        for (int nt = 0; nt < 4; nt++) {
            int cc = n0 + wn * 32 + nt * 8 + 2 * l4;
            float bx = 0.f, by = 0.f;
            if (bias) { bx = bias[cc]; by = bias[cc + 1]; }
            *(float2*)&C[(size_t)r0 * N + cc] =
                make_float2(acc[mt][nt][0] + bx, acc[mt][nt][1] + by);
            *(float2*)&C[(size_t)(r0 + 8) * N + cc] =
                make_float2(acc[mt][nt][2] + bx, acc[mt][nt][3] + by);
        }
    }
}

// ---------------------------------------------------------------------------
// K1: scores. Block=(qt64, b, h), 256 thr, warps 2(m)x4(n), warp tile 32x32.
// Q/K in smem hi/lo-packed permuted layout: slot(row, ks, l4) ->
// float4 {hi(kk), lo(kk), hi(kk+4), lo(kk+4)}, kk=ks*8+l4, row stride 144.
// Writes raw masked scores to the attn region of d_out.
// ---------------------------------------------------------------------------
#define QT1 64
#define QSTR 144

__device__ __forceinline__ void stage_hilo(const float* __restrict__ src0,
                                           float* __restrict__ dst,
                                           int tid, int rot, int iters)
{
#pragma unroll
    for (int i = 0; i < 8; i++) {
        if (i >= iters) break;
        int idx = tid + i * 256;
        int row = idx >> 4, c4 = (idx & 15) * 4;
        float4 v = *(const float4*)&src0[(size_t)row * DD + c4];
        float f0 = v.x, f1 = v.y, f2 = v.z, f3 = v.w;
        int ks = c4 >> 3, j = (c4 >> 2) & 1;
        float* base = dst + row * QSTR + ks * 16 + j * 2;
#pragma unroll
        for (int k = 0; k < 4; k++) {
            int p = (k + rot) & 3;
            float fv = (p == 0) ? f0 : (p == 1) ? f1 : (p == 2) ? f2 : f3;
            uint32_t hi = tf32r(fv);
            *(float2*)(base + p * 4) = make_float2(
                __uint_as_float(hi),
                __uint_as_float(tf32r(fv - __uint_as_float(hi))));
        }
    }
}

__global__ __launch_bounds__(256)
void score_kernel(const float* __restrict__ Q, const float* __restrict__ K,
                  const int* __restrict__ mask, const float* __restrict__ pb,
                  float* __restrict__ Sout)
{
    extern __shared__ float sm[];
    float* Qs = sm;                  // QT1 * QSTR
    float* Ks = sm + QT1 * QSTR;     // 128 * QSTR

    const int tid = threadIdx.x;
    const int lane = tid & 31, w = tid >> 5;
    const int g = lane >> 2, l4 = lane & 3;
    const int wm = w >> 2, wn = w & 3;
    const int qt = blockIdx.x, b = blockIdx.y, h = blockIdx.z;
    const int q0 = qt * QT1;
    const int rot = (lane >> 2) & 3;

    stage_hilo(&Q[(size_t)(b*SS + q0) * DD + h*DKK], Qs, tid, rot, 4);

    float acc[2][4][4];
#pragma unroll
    for (int mt = 0; mt < 2; mt++)
#pragma unroll
        for (int nt = 0; nt < 4; nt++)
#pragma unroll
            for (int r = 0; r < 4; r++) acc[mt][nt][r] = 0.f;

    for (int kt = 0; kt < SS / 128; kt++) {
        __syncthreads();
        stage_hilo(&K[(size_t)(b*SS + kt*128) * DD + h*DKK], Ks, tid, rot, 8);
        __syncthreads();

#pragma unroll
        for (int ks = 0; ks < 8; ks++) {
            float4 qa[2][2];
#pragma unroll
            for (int mt = 0; mt < 2; mt++)
#pragma unroll
                for (int hh = 0; hh < 2; hh++)
                    qa[mt][hh] = *(float4*)&Qs[(wm*32 + mt*16 + g + 8*hh)*QSTR + ks*16 + l4*4];
#pragma unroll
            for (int nt = 0; nt < 4; nt++) {
                float4 kb = *(float4*)&Ks[(wn*32 + nt*8 + g)*QSTR + ks*16 + l4*4];
                uint32_t bh0 = __float_as_uint(kb.x), bl0 = __float_as_uint(kb.y);
                uint32_t bh1 = __float_as_uint(kb.z), bl1 = __float_as_uint(kb.w);
#pragma unroll
                for (int mt = 0; mt < 2; mt++) {
                    uint32_t ah0 = __float_as_uint(qa[mt][0].x), ah1 = __float_as_uint(qa[mt][1].x);
                    uint32_t ah2 = __float_as_uint(qa[mt][0].z), ah3 = __float_as_uint(qa[mt][1].z);
                    uint32_t al0 = __float_as_uint(qa[mt][0].y), al1 = __float_as_uint(qa[mt][1].y);
                    uint32_t al2 = __float_as_uint(qa[mt][0].w), al3 = __float_as_uint(qa[mt][1].w);
                    mma8(acc[mt][nt], al0, al1, al2, al3, bh0, bh1);
                    mma8(acc[mt][nt], ah0, ah1, ah2, ah3, bl0, bl1);
                    mma8(acc[mt][nt], ah0, ah1, ah2, ah3, bh0, bh1);
                }
            }
        }

        // epilogue for this key chunk
#pragma unroll
        for (int mt = 0; mt < 2; mt++) {
            int r0 = q0 + wm*32 + mt*16 + g;
            int r1 = r0 + 8;
#pragma unroll
            for (int nt = 0; nt < 4; nt++) {
                int col = kt*128 + wn*32 + nt*8 + 2*l4;
                float* a = acc[mt][nt];
                float2 pb0 = *(const float2*)&pb[((size_t)h*SS + r0) * SS + col];
                float2 pb1 = *(const float2*)&pb[((size_t)h*SS + r1) * SS + col];
                int2 mk0 = *(const int2*)&mask[((size_t)b*SS + r0) * SS + col];
                int2 mk1 = *(const int2*)&mask[((size_t)b*SS + r1) * SS + col];
                float2 s0, s1;
                s0.x = a[0] * 0.125f + pb0.x; if (mk0.x == 0) s0.x = -1e9f;
                s0.y = a[1] * 0.125f + pb0.y; if (mk0.y == 0) s0.y = -1e9f;
                s1.x = a[2] * 0.125f + pb1.x; if (mk1.x == 0) s1.x = -1e9f;
                s1.y = a[3] * 0.125f + pb1.y; if (mk1.y == 0) s1.y = -1e9f;
                *(float2*)&Sout[((size_t)(b*HH + h)*SS + r0) * SS + col] = s0;
                *(float2*)&Sout[((size_t)(b*HH + h)*SS + r1) * SS + col] = s1;
                a[0] = 0.f; a[1] = 0.f; a[2] = 0.f; a[3] = 0.f;
            }
        }
    }
}

// ---------------------------------------------------------------------------
// K2: row softmax in place. One 128-thread block per (b,h,q) row.
// ---------------------------------------------------------------------------
__global__ __launch_bounds__(128)
void softmax_kernel(float* __restrict__ S)
{
    __shared__ float red[8];
    const size_t base = (size_t)blockIdx.x * SS;
    const int tid = threadIdx.x;
    const int warp = tid >> 5, lane = tid & 31;

    float4 v[4];
#pragma unroll
    for (int i = 0; i < 4; i++)
        v[i] = *(const float4*)&S[base + i*512 + tid*4];

    float mx = -1e30f;
#pragma unroll
    for (int i = 0; i < 4; i++)
        mx = fmaxf(mx, fmaxf(fmaxf(v[i].x, v[i].y), fmaxf(v[i].z, v[i].w)));
#pragma unroll
    for (int o = 16; o; o >>= 1) mx = fmaxf(mx, __shfl_xor_sync(0xffffffffu, mx, o));
    if (lane == 0) red[warp] = mx;
    __syncthreads();
    mx = fmaxf(fmaxf(red[0], red[1]), fmaxf(red[2], red[3]));

    float sum = 0.f;
#pragma unroll
    for (int i = 0; i < 4; i++) {
        v[i].x = __expf(v[i].x - mx); v[i].y = __expf(v[i].y - mx);
        v[i].z = __expf(v[i].z - mx); v[i].w = __expf(v[i].w - mx);
        sum += (v[i].x + v[i].y) + (v[i].z + v[i].w);
    }
#pragma unroll
    for (int o = 16; o; o >>= 1) sum += __shfl_xor_sync(0xffffffffu, sum, o);
    if (lane == 0) red[4 + warp] = sum;
    __syncthreads();
    sum = (red[4] + red[5]) + (red[6] + red[7]);

    float rinv = 1.f / sum;
#pragma unroll
    for (int i = 0; i < 4; i++) {
        v[i].x *= rinv; v[i].y *= rinv; v[i].z *= rinv; v[i].w *= rinv;
        *(float4*)&S[base + i*512 + tid*4] = v[i];
    }
}

// ---------------------------------------------------------------------------
// K3: ctx = P @ V. Block=(qt128, b, h), 256 thr, warps 4(m)x2(n), tile 32x32.
// ---------------------------------------------------------------------------
#define PSTR 132
#define VSTR 68

__global__ __launch_bounds__(256)
void pv_kernel(const float* __restrict__ P, const float* __restrict__ V,
               float* __restrict__ ctx)
{
    extern __shared__ float sm[];
    float* Ps = sm;                 // 128 * PSTR
    float* Vs = sm + 128 * PSTR;    // 128 * VSTR

    const int tid = threadIdx.x;
    const int lane = tid & 31, w = tid >> 5;
    const int g = lane >> 2, l4 = lane & 3;
    const int wm = w >> 1, wn = w & 1;
    const int qt = blockIdx.x, b = blockIdx.y, h = blockIdx.z;
    const int q0 = qt * 128;

    float acc[2][4][4];
#pragma unroll
    for (int mt = 0; mt < 2; mt++)
#pragma unroll
        for (int nt = 0; nt < 4; nt++)
#pragma unroll
            for (int r = 0; r < 4; r++) acc[mt][nt][r] = 0.f;

    for (int kt = 0; kt < SS / 128; kt++) {
        __syncthreads();
#pragma unroll
        for (int i = 0; i < 16; i++) {
            int idx = tid + i * 256;
            int row = idx >> 5, c4 = (idx & 31) * 4;
            float4 v = *(const float4*)&P[((size_t)(b*HH + h)*SS + q0 + row) * SS + kt*128 + c4];
            v.x = tf32f(v.x); v.y = tf32f(v.y); v.z = tf32f(v.z); v.w = tf32f(v.w);
            *(float4*)&Ps[row * PSTR + c4] = v;
        }
#pragma unroll
        for (int i = 0; i < 8; i++) {
            int idx = tid + i * 256;
            int row = idx >> 4, c4 = (idx & 15) * 4;
            float4 v = *(const float4*)&V[(size_t)(b*SS + kt*128 + row) * DD + h*DKK + c4];
            v.x = tf32f(v.x); v.y = tf32f(v.y); v.z = tf32f(v.z); v.w = tf32f(v.w);
            *(float4*)&Vs[row * VSTR + c4] = v;
        }
        __syncthreads();

#pragma unroll
        for (int ks = 0; ks < 16; ks++) {
            uint32_t a[2][4];
#pragma unroll
            for (int mt = 0; mt < 2; mt++) {
                int r = wm*32 + mt*16 + g;
                a[mt][0] = __float_as_uint(Ps[r * PSTR + ks*8 + l4]);
                a[mt][1] = __float_as_uint(Ps[(r+8) * PSTR + ks*8 + l4]);
                a[mt][2] = __float_as_uint(Ps[r * PSTR + ks*8 + l4 + 4]);
                a[mt][3] = __float_as_uint(Ps[(r+8) * PSTR + ks*8 + l4 + 4]);
            }
#pragma unroll
            for (int nt = 0; nt < 4; nt++) {
                int col = wn*32 + nt*8 + g;
                uint32_t b0 = __float_as_uint(Vs[(ks*8 + l4) * VSTR + col]);
                uint32_t b1 = __float_as_uint(Vs[(ks*8 + l4 + 4) * VSTR + col]);
#pragma unroll
                for (int mt = 0; mt < 2; mt++)
                    mma8(acc[mt][nt], a[mt][0], a[mt][1], a[mt][2], a[mt][3], b0, b1);
            }
        }
    }

#pragma unroll
    for (int mt = 0; mt < 2; mt++) {
        int r0 = q0 + wm*32 + mt*16 + g;
#pragma unroll
        for (int nt = 0; nt < 4; nt++) {
            int cc = h*DKK + wn*32 + nt*8 + 2*l4;
            *(float2*)&ctx[(size_t)(b*SS + r0) * DD + cc] =
                make_float2(acc[mt][nt][0], acc[mt][nt][1]);
            *(float2*)&ctx[(size_t)(b*SS + r0 + 8) * DD + cc] =
                make_float2(acc[mt][nt][2], acc[mt][nt][3]);
        }
    }
}

// ---------------------------------------------------------------------------
// Launch
// ---------------------------------------------------------------------------
extern "C" void kernel_launch(void* const* d_in, const int* in_sizes, int n_in,
                              void* d_out, int out_size)
{
    const float* query = (const float*)d_in[0];
    const float* key   = (const float*)d_in[1];
    const float* value = (const float*)d_in[2];
    const int*   mask  = (const int*)  d_in[3];
    const float* pb    = (const float*)d_in[4];
    const float* Wq    = (const float*)d_in[5];
    const float* Wk    = (const float*)d_in[6];
    const float* Wv    = (const float*)d_in[7];
    const float* Wo    = (const float*)d_in[8];
    const float* bo    = (const float*)d_in[9];
    float* out = (float*)d_out;
    float* attn = out + OUT_OFF;

    float *pQ, *pK, *pV, *pC;
    cudaGetSymbolAddress((void**)&pQ, g_Q);
    cudaGetSymbolAddress((void**)&pK, g_K);
    cudaGetSymbolAddress((void**)&pV, g_V);
    cudaGetSymbolAddress((void**)&pC, g_ctx);

    const int SC_SMEM = (QT1 + 128) * QSTR * sizeof(float);        // 110592
    const int PV_SMEM = (128*PSTR + 128*VSTR) * sizeof(float);     // 102400
    cudaFuncSetAttribute(score_kernel,
                         cudaFuncAttributeMaxDynamicSharedMemorySize, SC_SMEM);
    cudaFuncSetAttribute(pv_kernel,
                         cudaFuncAttributeMaxDynamicSharedMemorySize, PV_SMEM);

    dim3 gg(DD / 128, NT / 128);
    gemm_tc<3><<<gg, 256>>>(query, Wq, pQ, nullptr, NT, DD, DD);
    gemm_tc<3><<<gg, 256>>>(key,   Wk, pK, nullptr, NT, DD, DD);
    gemm_tc<1><<<gg, 256>>>(value, Wv, pV, nullptr, NT, DD, DD);

    dim3 gs(SS / QT1, BB, HH);     // (32, 2, 12)
    score_kernel<<<gs, 256, SC_SMEM>>>(pQ, pK, mask, pb, attn);

    softmax_kernel<<<BB * HH * SS, 128>>>(attn);

    dim3 gp(SS / 128, BB, HH);     // (16, 2, 12)
    pv_kernel<<<gp, 256, PV_SMEM>>>(attn, pV, pC);

    gemm_tc<1><<<gg, 256>>>(pC, Wo, out, bo, NT, DD, DD);
}

// round 6
// speedup vs baseline: 3.4695x; 1.5610x over previous
#include <cuda_runtime.h>
#include <cuda_bf16.h>
#include <cstdint>

// Problem constants
#define BB 2
#define SS 2048
#define DD 768
#define HH 12
#define DKK 64
#define NT (BB*SS)
#define OUT_OFF ((size_t)BB*SS*DD)

// Scratch
__device__ float g_V[NT*DD];
__device__ float g_ctx[NT*DD];
// Packed split-bf16 Q/K: [token][head][pair(32)] as uint2 {hi bf16x2, lo bf16x2}
// (declared as uint4 for 16B alignment; NT*HH*32 uint2 = NT*HH*16 uint4)
__device__ uint4 g_Qp[NT*HH*16];
__device__ uint4 g_Kp[NT*HH*16];

// ---------------------------------------------------------------------------
// helpers
// ---------------------------------------------------------------------------
__device__ __forceinline__ uint32_t tf32r(float x) {
    uint32_t u; asm("cvt.rna.tf32.f32 %0, %1;" : "=r"(u) : "f"(x)); return u;
}
__device__ __forceinline__ float tf32f(float x) { return __uint_as_float(tf32r(x)); }

__device__ __forceinline__ void mma8(float* c,
    uint32_t a0, uint32_t a1, uint32_t a2, uint32_t a3, uint32_t b0, uint32_t b1)
{
    asm volatile(
        "mma.sync.aligned.m16n8k8.row.col.f32.tf32.tf32.f32 "
        "{%0,%1,%2,%3},{%4,%5,%6,%7},{%8,%9},{%0,%1,%2,%3};"
        : "+f"(c[0]), "+f"(c[1]), "+f"(c[2]), "+f"(c[3])
        : "r"(a0), "r"(a1), "r"(a2), "r"(a3), "r"(b0), "r"(b1));
}

__device__ __forceinline__ void mmabf(float* c,
    uint32_t a0, uint32_t a1, uint32_t a2, uint32_t a3, uint32_t b0, uint32_t b1)
{
    asm volatile(
        "mma.sync.aligned.m16n8k16.row.col.f32.bf16.bf16.f32 "
        "{%0,%1,%2,%3},{%4,%5,%6,%7},{%8,%9},{%0,%1,%2,%3};"
        : "+f"(c[0]), "+f"(c[1]), "+f"(c[2]), "+f"(c[3])
        : "r"(a0), "r"(a1), "r"(a2), "r"(a3), "r"(b0), "r"(b1));
}

// split-bf16 pack of (even, odd) element pair: .x = hi word, .y = lo word
__device__ __forceinline__ uint2 splitpack(float e, float o) {
    __nv_bfloat16 he = __float2bfloat16_rn(e), ho = __float2bfloat16_rn(o);
    float re = e - __bfloat162float(he);
    float ro = o - __bfloat162float(ho);
    __nv_bfloat16 le = __float2bfloat16_rn(re), lo = __float2bfloat16_rn(ro);
    uint2 r;
    r.x = (uint32_t)__bfloat16_as_ushort(he) | ((uint32_t)__bfloat16_as_ushort(ho) << 16);
    r.y = (uint32_t)__bfloat16_as_ushort(le) | ((uint32_t)__bfloat16_as_ushort(lo) << 16);
    return r;
}

// ---------------------------------------------------------------------------
// tf32 GEMM (V projection / output GEMM): C[m,n] = sum_k X[m,k]*W[n,k] (+bias)
// ---------------------------------------------------------------------------
__global__ __launch_bounds__(256)
void gemm_tc(const float* __restrict__ X, const float* __restrict__ W,
             float* __restrict__ C, const float* __restrict__ bias,
             int M, int N, int K)
{
    __shared__ float As[16][132];
    __shared__ float Bs[16][132];

    const int tid  = threadIdx.x;
    const int lane = tid & 31, warp = tid >> 5;
    const int g = lane >> 2, l4 = lane & 3;
    const int wm = warp >> 2, wn = warp & 3;
    const int m0 = blockIdx.y * 128, n0 = blockIdx.x * 128;

    float acc[4][4][4];
#pragma unroll
    for (int i = 0; i < 4; i++)
#pragma unroll
        for (int j = 0; j < 4; j++)
#pragma unroll
            for (int r = 0; r < 4; r++) acc[i][j][r] = 0.f;

    for (int k0 = 0; k0 < K; k0 += 16) {
#pragma unroll
        for (int i = 0; i < 2; i++) {
            int ii = tid + i * 256;
            int row = ii >> 2, kg = (ii & 3) * 4;
            float4 av = *(const float4*)&X[(size_t)(m0 + row) * K + k0 + kg];
            float4 bv = *(const float4*)&W[(size_t)(n0 + row) * K + k0 + kg];
            As[kg+0][row] = tf32f(av.x); As[kg+1][row] = tf32f(av.y);
            As[kg+2][row] = tf32f(av.z); As[kg+3][row] = tf32f(av.w);
            Bs[kg+0][row] = tf32f(bv.x); Bs[kg+1][row] = tf32f(bv.y);
            Bs[kg+2][row] = tf32f(bv.z); Bs[kg+3][row] = tf32f(bv.w);
        }
        __syncthreads();

#pragma unroll
        for (int ks = 0; ks < 2; ks++) {
            uint32_t ah[4][4], bh[4][2];
#pragma unroll
            for (int mt = 0; mt < 4; mt++) {
                int rb = wm * 64 + mt * 16;
                ah[mt][0] = __float_as_uint(As[ks*8 + l4][rb + g]);
                ah[mt][1] = __float_as_uint(As[ks*8 + l4][rb + g + 8]);
                ah[mt][2] = __float_as_uint(As[ks*8 + l4 + 4][rb + g]);
                ah[mt][3] = __float_as_uint(As[ks*8 + l4 + 4][rb + g + 8]);
            }
#pragma unroll
            for (int nt = 0; nt < 4; nt++) {
                int cb = wn * 32 + nt * 8;
                bh[nt][0] = __float_as_uint(Bs[ks*8 + l4][cb + g]);
                bh[nt][1] = __float_as_uint(Bs[ks*8 + l4 + 4][cb + g]);
            }
#pragma unroll
            for (int mt = 0; mt < 4; mt++)
#pragma unroll
                for (int nt = 0; nt < 4; nt++)
                    mma8(acc[mt][nt], ah[mt][0], ah[mt][1], ah[mt][2], ah[mt][3],
                         bh[nt][0], bh[nt][1]);
        }
        __syncthreads();
    }

#pragma unroll
    for (int mt = 0; mt < 4; mt++) {
        int r0 = m0 + wm * 64 + mt * 16 + g;
#pragma unroll
        for (int nt = 0; nt < 4; nt++) {
            int cc = n0 + wn * 32 + nt * 8 + 2 * l4;
            float bx = 0.f, by = 0.f;
            if (bias) { bx = bias[cc]; by = bias[cc + 1]; }
            *(float2*)&C[(size_t)r0 * N + cc] =
                make_float2(acc[mt][nt][0] + bx, acc[mt][nt][1] + by);
            *(float2*)&C[(size_t)(r0 + 8) * N + cc] =
                make_float2(acc[mt][nt][2] + bx, acc[mt][nt][3] + by);
        }
    }
}

// ---------------------------------------------------------------------------
// split-bf16 GEMM for Q/K projections: writes PACKED hi/lo output only.
// 128x128 tile, 256 threads, warp tile 64x32, k-chunk 16 (8 pairs).
// smem layout: word[row][p ^ ((row>>1&1)<<2)], row stride 8 uint2 (64B).
// ---------------------------------------------------------------------------
__global__ __launch_bounds__(256)
void gemm_bf_pack(const float* __restrict__ X, const float* __restrict__ W,
                  uint2* __restrict__ OutPack, int M, int N, int K)
{
    __shared__ uint2 As[128*8];
    __shared__ uint2 Bs[128*8];

    const int tid  = threadIdx.x;
    const int lane = tid & 31, warp = tid >> 5;
    const int g = lane >> 2, l4 = lane & 3;
    const int wm = warp >> 2, wn = warp & 3;
    const int m0 = blockIdx.y * 128, n0 = blockIdx.x * 128;

    float acc[4][4][4];
#pragma unroll
    for (int i = 0; i < 4; i++)
#pragma unroll
        for (int j = 0; j < 4; j++)
#pragma unroll
            for (int r = 0; r < 4; r++) acc[i][j][r] = 0.f;

    for (int k0 = 0; k0 < K; k0 += 16) {
#pragma unroll
        for (int i = 0; i < 2; i++) {
            int ii = tid + i * 256;
            int row = ii >> 2, kg = (ii & 3) * 4;
            float4 av = *(const float4*)&X[(size_t)(m0 + row) * K + k0 + kg];
            float4 bv = *(const float4*)&W[(size_t)(n0 + row) * K + k0 + kg];
            int p0 = kg >> 1;                 // even pair index
            int sw = ((row >> 1) & 1) << 2;
            uint2 wa0 = splitpack(av.x, av.y), wa1 = splitpack(av.z, av.w);
            uint2 wb0 = splitpack(bv.x, bv.y), wb1 = splitpack(bv.z, bv.w);
            *(uint4*)&As[row*8 + (p0 ^ sw)] = make_uint4(wa0.x, wa0.y, wa1.x, wa1.y);
            *(uint4*)&Bs[row*8 + (p0 ^ sw)] = make_uint4(wb0.x, wb0.y, wb1.x, wb1.y);
        }
        __syncthreads();

        uint2 bf[4][2];
#pragma unroll
        for (int nt = 0; nt < 4; nt++) {
            int cb = wn * 32 + nt * 8 + g;
            int sb = ((cb >> 1) & 1) << 2;
            bf[nt][0] = Bs[cb*8 + (l4 ^ sb)];
            bf[nt][1] = Bs[cb*8 + ((l4 + 4) ^ sb)];
        }
#pragma unroll
        for (int mt = 0; mt < 4; mt++) {
            int r = wm * 64 + mt * 16 + g;
            int sa = ((r >> 1) & 1) << 2;
            uint2 a0 = As[r*8 + (l4 ^ sa)];
            uint2 a1 = As[(r+8)*8 + (l4 ^ sa)];
            uint2 a2 = As[r*8 + ((l4 + 4) ^ sa)];
            uint2 a3 = As[(r+8)*8 + ((l4 + 4) ^ sa)];
#pragma unroll
            for (int nt = 0; nt < 4; nt++) {
                mmabf(acc[mt][nt], a0.x, a1.x, a2.x, a3.x, bf[nt][0].y, bf[nt][1].y);
                mmabf(acc[mt][nt], a0.y, a1.y, a2.y, a3.y, bf[nt][0].x, bf[nt][1].x);
                mmabf(acc[mt][nt], a0.x, a1.x, a2.x, a3.x, bf[nt][0].x, bf[nt][1].x);
            }
        }
        __syncthreads();
    }

    // epilogue: pack to [token][head][pair] uint2
#pragma unroll
    for (int mt = 0; mt < 4; mt++) {
        int r0 = m0 + wm * 64 + mt * 16 + g;
#pragma unroll
        for (int nt = 0; nt < 4; nt++) {
            int cc = n0 + wn * 32 + nt * 8 + 2 * l4;
            int h = cc >> 6, pg = (cc >> 1) & 31;
            OutPack[((size_t)r0 * HH + h) * 32 + pg] =
                splitpack(acc[mt][nt][0], acc[mt][nt][1]);
            OutPack[((size_t)(r0 + 8) * HH + h) * 32 + pg] =
                splitpack(acc[mt][nt][2], acc[mt][nt][3]);
        }
    }
}

// ---------------------------------------------------------------------------
// K1: scores, split-bf16. Block=(qt64, b, h), 256 thr, warps 2(m)x4(n),
// warp tile 32x32, K chunk 128 keys. smem: packed words,
// index = row*32 + (pair ^ ((row&3)<<2)). 48KB total.
// ---------------------------------------------------------------------------
__global__ __launch_bounds__(256)
void score_bf(const uint2* __restrict__ Qp, const uint2* __restrict__ Kp,
              const int* __restrict__ mask, const float* __restrict__ pb,
              float* __restrict__ Sout)
{
    extern __shared__ uint4 smraw[];
    uint2* sQ = (uint2*)smraw;           // 64*32
    uint2* sK = (uint2*)smraw + 64*32;   // 128*32

    const int tid = threadIdx.x;
    const int lane = tid & 31, w = tid >> 5;
    const int g = lane >> 2, l4 = lane & 3;
    const int wm = w >> 2, wn = w & 3;
    const int qt = blockIdx.x, b = blockIdx.y, h = blockIdx.z;
    const int q0 = qt * 64;

    // stage Q (pure copy, swizzled)
    {
        const uint4* qsrc = (const uint4*)(Qp + ((size_t)(b*SS + q0) * HH + h) * 32);
#pragma unroll
        for (int i = 0; i < 4; i++) {
            int idx = tid + i * 256;          // 1024 uint4
            int row = idx >> 4, p2 = (idx & 15) * 2;
            uint4 v = qsrc[(size_t)row * (HH*16) + (p2 >> 1)];
            int sw = (row & 3) << 2;
            *(uint4*)&sQ[row*32 + (p2 ^ sw)] = v;
        }
    }

    float acc[2][4][4];
#pragma unroll
    for (int mt = 0; mt < 2; mt++)
#pragma unroll
        for (int nt = 0; nt < 4; nt++)
#pragma unroll
            for (int r = 0; r < 4; r++) acc[mt][nt][r] = 0.f;

    for (int kt = 0; kt < SS / 128; kt++) {
        __syncthreads();
        const uint4* ksrc = (const uint4*)(Kp + ((size_t)(b*SS + kt*128) * HH + h) * 32);
#pragma unroll
        for (int i = 0; i < 8; i++) {
            int idx = tid + i * 256;          // 2048 uint4
            int row = idx >> 4, p2 = (idx & 15) * 2;
            uint4 v = ksrc[(size_t)row * (HH*16) + (p2 >> 1)];
            int sw = (row & 3) << 2;
            *(uint4*)&sK[row*32 + (p2 ^ sw)] = v;
        }
        __syncthreads();

#pragma unroll
        for (int s = 0; s < 4; s++) {
            uint2 qa[2][4];
#pragma unroll
            for (int mt = 0; mt < 2; mt++) {
                int r = wm*32 + mt*16 + g;
                int sa = (r & 3) << 2;
                qa[mt][0] = sQ[r*32 + ((8*s + l4) ^ sa)];
                qa[mt][1] = sQ[(r+8)*32 + ((8*s + l4) ^ sa)];
                qa[mt][2] = sQ[r*32 + ((8*s + l4 + 4) ^ sa)];
                qa[mt][3] = sQ[(r+8)*32 + ((8*s + l4 + 4) ^ sa)];
            }
#pragma unroll
            for (int nt = 0; nt < 4; nt++) {
                int key = wn*32 + nt*8 + g;
                int sb = (key & 3) << 2;
                uint2 b0 = sK[key*32 + ((8*s + l4) ^ sb)];
                uint2 b1 = sK[key*32 + ((8*s + l4 + 4) ^ sb)];
#pragma unroll
                for (int mt = 0; mt < 2; mt++) {
                    mmabf(acc[mt][nt], qa[mt][0].x, qa[mt][1].x, qa[mt][2].x, qa[mt][3].x,
                          b0.y, b1.y);
                    mmabf(acc[mt][nt], qa[mt][0].y, qa[mt][1].y, qa[mt][2].y, qa[mt][3].y,
                          b0.x, b1.x);
                    mmabf(acc[mt][nt], qa[mt][0].x, qa[mt][1].x, qa[mt][2].x, qa[mt][3].x,
                          b0.x, b1.x);
                }
            }
        }

        // epilogue for this key chunk
#pragma unroll
        for (int mt = 0; mt < 2; mt++) {
            int r0 = q0 + wm*32 + mt*16 + g;
            int r1 = r0 + 8;
#pragma unroll
            for (int nt = 0; nt < 4; nt++) {
                int col = kt*128 + wn*32 + nt*8 + 2*l4;
                float* a = acc[mt][nt];
                float2 pb0 = *(const float2*)&pb[((size_t)h*SS + r0) * SS + col];
                float2 pb1 = *(const float2*)&pb[((size_t)h*SS + r1) * SS + col];
                int2 mk0 = *(const int2*)&mask[((size_t)b*SS + r0) * SS + col];
                int2 mk1 = *(const int2*)&mask[((size_t)b*SS + r1) * SS + col];
                float2 s0, s1;
                s0.x = a[0] * 0.125f + pb0.x; if (mk0.x == 0) s0.x = -1e9f;
                s0.y = a[1] * 0.125f + pb0.y; if (mk0.y == 0) s0.y = -1e9f;
                s1.x = a[2] * 0.125f + pb1.x; if (mk1.x == 0) s1.x = -1e9f;
                s1.y = a[3] * 0.125f + pb1.y; if (mk1.y == 0) s1.y = -1e9f;
                *(float2*)&Sout[((size_t)(b*HH + h)*SS + r0) * SS + col] = s0;
                *(float2*)&Sout[((size_t)(b*HH + h)*SS + r1) * SS + col] = s1;
                a[0] = 0.f; a[1] = 0.f; a[2] = 0.f; a[3] = 0.f;
            }
        }
    }
}

// ---------------------------------------------------------------------------
// K2: row softmax in place. One 128-thread block per (b,h,q) row.
// ---------------------------------------------------------------------------
__global__ __launch_bounds__(128)
void softmax_kernel(float* __restrict__ S)
{
    __shared__ float red[8];
    const size_t base = (size_t)blockIdx.x * SS;
    const int tid = threadIdx.x;
    const int warp = tid >> 5, lane = tid & 31;

    float4 v[4];
#pragma unroll
    for (int i = 0; i < 4; i++)
        v[i] = *(const float4*)&S[base + i*512 + tid*4];

    float mx = -1e30f;
#pragma unroll
    for (int i = 0; i < 4; i++)
        mx = fmaxf(mx, fmaxf(fmaxf(v[i].x, v[i].y), fmaxf(v[i].z, v[i].w)));
#pragma unroll
    for (int o = 16; o; o >>= 1) mx = fmaxf(mx, __shfl_xor_sync(0xffffffffu, mx, o));
    if (lane == 0) red[warp] = mx;
    __syncthreads();
    mx = fmaxf(fmaxf(red[0], red[1]), fmaxf(red[2], red[3]));

    float sum = 0.f;
#pragma unroll
    for (int i = 0; i < 4; i++) {
        v[i].x = __expf(v[i].x - mx); v[i].y = __expf(v[i].y - mx);
        v[i].z = __expf(v[i].z - mx); v[i].w = __expf(v[i].w - mx);
        sum += (v[i].x + v[i].y) + (v[i].z + v[i].w);
    }
#pragma unroll
    for (int o = 16; o; o >>= 1) sum += __shfl_xor_sync(0xffffffffu, sum, o);
    if (lane == 0) red[4 + warp] = sum;
    __syncthreads();
    sum = (red[4] + red[5]) + (red[6] + red[7]);

    float rinv = 1.f / sum;
#pragma unroll
    for (int i = 0; i < 4; i++) {
        v[i].x *= rinv; v[i].y *= rinv; v[i].z *= rinv; v[i].w *= rinv;
        *(float4*)&S[base + i*512 + tid*4] = v[i];
    }
}

// ---------------------------------------------------------------------------
// K3: ctx = P @ V (tf32). Block=(qt128, b, h), 256 thr, warps 4(m)x2(n).
// ---------------------------------------------------------------------------
#define PSTR 132
#define VSTR 68

__global__ __launch_bounds__(256)
void pv_kernel(const float* __restrict__ P, const float* __restrict__ V,
               float* __restrict__ ctx)
{
    extern __shared__ float sm[];
    float* Ps = sm;                 // 128 * PSTR
    float* Vs = sm + 128 * PSTR;    // 128 * VSTR

    const int tid = threadIdx.x;
    const int lane = tid & 31, w = tid >> 5;
    const int g = lane >> 2, l4 = lane & 3;
    const int wm = w >> 1, wn = w & 1;
    const int qt = blockIdx.x, b = blockIdx.y, h = blockIdx.z;
    const int q0 = qt * 128;

    float acc[2][4][4];
#pragma unroll
    for (int mt = 0; mt < 2; mt++)
#pragma unroll
        for (int nt = 0; nt < 4; nt++)
#pragma unroll
            for (int r = 0; r < 4; r++) acc[mt][nt][r] = 0.f;

    for (int kt = 0; kt < SS / 128; kt++) {
        __syncthreads();
#pragma unroll
        for (int i = 0; i < 16; i++) {
            int idx = tid + i * 256;
            int row = idx >> 5, c4 = (idx & 31) * 4;
            float4 v = *(const float4*)&P[((size_t)(b*HH + h)*SS + q0 + row) * SS + kt*128 + c4];
            v.x = tf32f(v.x); v.y = tf32f(v.y); v.z = tf32f(v.z); v.w = tf32f(v.w);
            *(float4*)&Ps[row * PSTR + c4] = v;
        }
#pragma unroll
        for (int i = 0; i < 8; i++) {
            int idx = tid + i * 256;
            int row = idx >> 4, c4 = (idx & 15) * 4;
            float4 v = *(const float4*)&V[(size_t)(b*SS + kt*128 + row) * DD + h*DKK + c4];
            v.x = tf32f(v.x); v.y = tf32f(v.y); v.z = tf32f(v.z); v.w = tf32f(v.w);
            *(float4*)&Vs[row * VSTR + c4] = v;
        }
        __syncthreads();

#pragma unroll
        for (int ks = 0; ks < 16; ks++) {
            uint32_t a[2][4];
#pragma unroll
            for (int mt = 0; mt < 2; mt++) {
                int r = wm*32 + mt*16 + g;
                a[mt][0] = __float_as_uint(Ps[r * PSTR + ks*8 + l4]);
                a[mt][1] = __float_as_uint(Ps[(r+8) * PSTR + ks*8 + l4]);
                a[mt][2] = __float_as_uint(Ps[r * PSTR + ks*8 + l4 + 4]);
                a[mt][3] = __float_as_uint(Ps[(r+8) * PSTR + ks*8 + l4 + 4]);
            }
#pragma unroll
            for (int nt = 0; nt < 4; nt++) {
                int col = wn*32 + nt*8 + g;
                uint32_t b0 = __float_as_uint(Vs[(ks*8 + l4) * VSTR + col]);
                uint32_t b1 = __float_as_uint(Vs[(ks*8 + l4 + 4) * VSTR + col]);
#pragma unroll
                for (int mt = 0; mt < 2; mt++)
                    mma8(acc[mt][nt], a[mt][0], a[mt][1], a[mt][2], a[mt][3], b0, b1);
            }
        }
    }

#pragma unroll
    for (int mt = 0; mt < 2; mt++) {
        int r0 = q0 + wm*32 + mt*16 + g;
#pragma unroll
        for (int nt = 0; nt < 4; nt++) {
            int cc = h*DKK + wn*32 + nt*8 + 2*l4;
            *(float2*)&ctx[(size_t)(b*SS + r0) * DD + cc] =
                make_float2(acc[mt][nt][0], acc[mt][nt][1]);
            *(float2*)&ctx[(size_t)(b*SS + r0 + 8) * DD + cc] =
                make_float2(acc[mt][nt][2], acc[mt][nt][3]);
        }
    }
}

// ---------------------------------------------------------------------------
// Launch
// ---------------------------------------------------------------------------
extern "C" void kernel_launch(void* const* d_in, const int* in_sizes, int n_in,
                              void* d_out, int out_size)
{
    const float* query = (const float*)d_in[0];
    const float* key   = (const float*)d_in[1];
    const float* value = (const float*)d_in[2];
    const int*   mask  = (const int*)  d_in[3];
    const float* pb    = (const float*)d_in[4];
    const float* Wq    = (const float*)d_in[5];
    const float* Wk    = (const float*)d_in[6];
    const float* Wv    = (const float*)d_in[7];
    const float* Wo    = (const float*)d_in[8];
    const float* bo    = (const float*)d_in[9];
    float* out = (float*)d_out;
    float* attn = out + OUT_OFF;

    float *pV, *pC;
    uint4 *pQp, *pKp;
    cudaGetSymbolAddress((void**)&pV,  g_V);
    cudaGetSymbolAddress((void**)&pC,  g_ctx);
    cudaGetSymbolAddress((void**)&pQp, g_Qp);
    cudaGetSymbolAddress((void**)&pKp, g_Kp);

    const int SC_SMEM = (64*32 + 128*32) * sizeof(uint2);          // 49152
    const int PV_SMEM = (128*PSTR + 128*VSTR) * sizeof(float);     // 102400
    cudaFuncSetAttribute(score_bf,
                         cudaFuncAttributeMaxDynamicSharedMemorySize, SC_SMEM);
    cudaFuncSetAttribute(pv_kernel,
                         cudaFuncAttributeMaxDynamicSharedMemorySize, PV_SMEM);

    dim3 gg(DD / 128, NT / 128);   // (6, 32)
    gemm_bf_pack<<<gg, 256>>>(query, Wq, (uint2*)pQp, NT, DD, DD);
    gemm_bf_pack<<<gg, 256>>>(key,   Wk, (uint2*)pKp, NT, DD, DD);
    gemm_tc<<<gg, 256>>>(value, Wv, pV, nullptr, NT, DD, DD);

    dim3 gs(SS / 64, BB, HH);      // (32, 2, 12) — h slowest for L2 reuse
    score_bf<<<gs, 256, SC_SMEM>>>((const uint2*)pQp, (const uint2*)pKp,
                                   mask, pb, attn);

    softmax_kernel<<<BB * HH * SS, 128>>>(attn);

    dim3 gp(SS / 128, BB, HH);     // (16, 2, 12)
    pv_kernel<<<gp, 256, PV_SMEM>>>(attn, pV, pC);

    gemm_tc<<<gg, 256>>>(pC, Wo, out, bo, NT, DD, DD);
}